// round 5
// baseline (speedup 1.0000x reference)
#include <cuda_runtime.h>
#include <math.h>
#include <stdint.h>

#define B_  32
#define N_  1024
#define D_  256
#define NEGMASK (-9.0e15f)
#define ALPHA_  0.2f

// ---------------- device scratch ----------------
__device__ float g_zt[B_ * N_ * D_];     // zt [b][d][j]  (tf32-rounded)
__device__ float g_s1[B_ * N_];
__device__ float g_s2[B_ * N_];
__device__ float g_s1p[4][B_ * N_];      // partials (bn*2+wc)
__device__ float g_s2p[4][B_ * N_];
__device__ float g_m [B_ * N_];
__device__ float g_linv[B_ * N_];
__device__ unsigned g_bits[B_ * N_ * 32];  // adj bitmask

// ---------------- helpers ----------------
__device__ __forceinline__ uint32_t smem_u32(const void* p) {
    uint32_t a;
    asm("{ .reg .u64 t; cvta.to.shared.u64 t, %1; cvt.u32.u64 %0, t; }" : "=r"(a) : "l"(p));
    return a;
}
__device__ __forceinline__ uint32_t tf32u(float f) {
    uint32_t u; asm("cvt.rna.tf32.f32 %0, %1;" : "=r"(u) : "f"(f));
    return u;
}
__device__ __forceinline__ float tf32f(float f) { return __uint_as_float(tf32u(f)); }

#define CP_ASYNC16(sm, gp) \
    asm volatile("cp.async.cg.shared.global [%0], [%1], 16;" :: "r"(sm), "l"(gp) : "memory")
#define CP_COMMIT()  asm volatile("cp.async.commit_group;" ::: "memory")
#define CP_WAIT0()   asm volatile("cp.async.wait_group 0;" ::: "memory")
#define CP_WAIT1()   asm volatile("cp.async.wait_group 1;" ::: "memory")

__device__ __forceinline__ void mma_tf32(float* c, uint32_t a0, uint32_t a1,
                                         uint32_t a2, uint32_t a3,
                                         uint32_t b0, uint32_t b1) {
    asm volatile(
        "mma.sync.aligned.m16n8k8.row.col.f32.tf32.tf32.f32 "
        "{%0,%1,%2,%3}, {%4,%5,%6,%7}, {%8,%9}, {%0,%1,%2,%3};"
        : "+f"(c[0]), "+f"(c[1]), "+f"(c[2]), "+f"(c[3])
        : "r"(a0), "r"(a1), "r"(a2), "r"(a3), "r"(b0), "r"(b1));
}

// ---------------------------------------------------------------------------
// Kernel 1: fused z-GEMM (3xTF32, ~fp32 precision) + bias + s1/s2 partials
//           + transposed tf32 zt store.  CTA = 128 rows x 128 cols.
// grid (bn=2, bm=256), 256 threads, 8 warps of 32x64.
// smem: double-buffered A[128][36], B[128][36] fp32; stage tile reuses buf0.
// ---------------------------------------------------------------------------
#define ZG_BUF  9216                    // floats per buffer (A 4608 + B 4608)
#define ZG_SMEMB (2 * ZG_BUF * 4)       // 73728 bytes

__global__ __launch_bounds__(256) void k_zgemm_tc(const float* __restrict__ h,
                                                  const float* __restrict__ W,
                                                  const float* __restrict__ bias,
                                                  const float* __restrict__ av) {
    extern __shared__ __align__(16) float sm[];
    const int t    = threadIdx.x;
    const int lane = t & 31;
    const int wid  = t >> 5;
    const int wr   = wid & 3;
    const int wc   = wid >> 2;
    const int g    = lane >> 2;
    const int tq   = lane & 3;

    const int bn = blockIdx.x;          // d-half
    const int bm = blockIdx.y;          // row block
    const int R0 = bm * 128;            // global row (b*1024 + j)
    const uint32_t sb = smem_u32(sm);

    const float* hA = h + (size_t)R0 * D_;
    const float* wB = W + (size_t)(bn * 128) * D_;

    float acc[2][8][4];
#pragma unroll
    for (int mt = 0; mt < 2; mt++)
#pragma unroll
        for (int nt = 0; nt < 8; nt++)
#pragma unroll
            for (int q = 0; q < 4; q++) acc[mt][nt][q] = 0.f;

    // ---- prologue: chunk 0 -> buf 0
#pragma unroll
    for (int q = 0; q < 4; q++) {
        int idx = t + 256 * q, r = idx >> 3, s = idx & 7;
        CP_ASYNC16(sb + (0 + r * 36 + s * 4) * 4,    hA + (size_t)r * D_ + s * 4);
        CP_ASYNC16(sb + (4608 + r * 36 + s * 4) * 4, wB + (size_t)r * D_ + s * 4);
    }
    CP_COMMIT();

    for (int kc = 0; kc < 8; kc++) {
        if (kc < 7) {
            uint32_t bo = ((kc + 1) & 1) * ZG_BUF;
#pragma unroll
            for (int q = 0; q < 4; q++) {
                int idx = t + 256 * q, r = idx >> 3, s = idx & 7;
                CP_ASYNC16(sb + (bo + r * 36 + s * 4) * 4,
                           hA + (size_t)r * D_ + (kc + 1) * 32 + s * 4);
                CP_ASYNC16(sb + (bo + 4608 + r * 36 + s * 4) * 4,
                           wB + (size_t)r * D_ + (kc + 1) * 32 + s * 4);
            }
            CP_COMMIT();
            CP_WAIT1();
        } else {
            CP_WAIT0();
        }
        __syncthreads();

        const int aofs = (kc & 1) * ZG_BUF;
        const int bofs = aofs + 4608;
#pragma unroll
        for (int k0 = 0; k0 < 32; k0 += 8) {
            uint32_t bh[8][2], bl[8][2];
#pragma unroll
            for (int nt = 0; nt < 8; nt++) {
                int base = bofs + (wc * 64 + nt * 8 + g) * 36 + k0 + tq;
                float f0 = sm[base], f1 = sm[base + 4];
                bh[nt][0] = tf32u(f0);
                bl[nt][0] = tf32u(f0 - __uint_as_float(bh[nt][0]));
                bh[nt][1] = tf32u(f1);
                bl[nt][1] = tf32u(f1 - __uint_as_float(bh[nt][1]));
            }
#pragma unroll
            for (int mt = 0; mt < 2; mt++) {
                int ab = aofs + (wr * 32 + mt * 16 + g) * 36 + k0 + tq;
                float f0 = sm[ab],          f1 = sm[ab + 8 * 36];
                float f2 = sm[ab + 4],      f3 = sm[ab + 8 * 36 + 4];
                uint32_t ah0 = tf32u(f0), al0 = tf32u(f0 - __uint_as_float(ah0));
                uint32_t ah1 = tf32u(f1), al1 = tf32u(f1 - __uint_as_float(ah1));
                uint32_t ah2 = tf32u(f2), al2 = tf32u(f2 - __uint_as_float(ah2));
                uint32_t ah3 = tf32u(f3), al3 = tf32u(f3 - __uint_as_float(ah3));
#pragma unroll
                for (int nt = 0; nt < 8; nt++) {
                    mma_tf32(acc[mt][nt], ah0, ah1, ah2, ah3, bh[nt][0], bh[nt][1]);
                    mma_tf32(acc[mt][nt], ah0, ah1, ah2, ah3, bl[nt][0], bl[nt][1]);
                    mma_tf32(acc[mt][nt], al0, al1, al2, al3, bh[nt][0], bh[nt][1]);
                }
            }
        }
        __syncthreads();
    }

    // ---- epilogue: bias + s1/s2 partial dots
    float s1g[2] = {0.f, 0.f}, s1h[2] = {0.f, 0.f};
    float s2g[2] = {0.f, 0.f}, s2h[2] = {0.f, 0.f};
    const int colbase = bn * 128 + wc * 64;
#pragma unroll
    for (int nt = 0; nt < 8; nt++) {
        int c0 = colbase + nt * 8 + 2 * tq;
        float b0  = __ldg(bias + c0),        b1  = __ldg(bias + c0 + 1);
        float a10 = __ldg(av + c0),          a11 = __ldg(av + c0 + 1);
        float a20 = __ldg(av + D_ + c0),     a21 = __ldg(av + D_ + c0 + 1);
#pragma unroll
        for (int mt = 0; mt < 2; mt++) {
            acc[mt][nt][0] += b0; acc[mt][nt][1] += b1;
            acc[mt][nt][2] += b0; acc[mt][nt][3] += b1;
            s1g[mt] += acc[mt][nt][0] * a10 + acc[mt][nt][1] * a11;
            s1h[mt] += acc[mt][nt][2] * a10 + acc[mt][nt][3] * a11;
            s2g[mt] += acc[mt][nt][0] * a20 + acc[mt][nt][1] * a21;
            s2h[mt] += acc[mt][nt][2] * a20 + acc[mt][nt][3] * a21;
        }
    }
#pragma unroll
    for (int o = 1; o <= 2; o <<= 1) {
#pragma unroll
        for (int mt = 0; mt < 2; mt++) {
            s1g[mt] += __shfl_xor_sync(0xffffffffu, s1g[mt], o);
            s1h[mt] += __shfl_xor_sync(0xffffffffu, s1h[mt], o);
            s2g[mt] += __shfl_xor_sync(0xffffffffu, s2g[mt], o);
            s2h[mt] += __shfl_xor_sync(0xffffffffu, s2h[mt], o);
        }
    }
    if (tq == 0) {
        int part = bn * 2 + wc;
#pragma unroll
        for (int mt = 0; mt < 2; mt++) {
            int row = R0 + wr * 32 + mt * 16 + g;
            g_s1p[part][row]     = s1g[mt];
            g_s1p[part][row + 8] = s1h[mt];
            g_s2p[part][row]     = s2g[mt];
            g_s2p[part][row + 8] = s2h[mt];
        }
    }

    // ---- transposed tf32 zt store via smem staging (16 d x 128 j, reuse buf0)
    const int b_    = R0 >> 10;
    const int jbase = R0 & 1023;
    float* zt = g_zt + ((size_t)b_ << 18);
#pragma unroll 1
    for (int nt = 0; nt < 8; nt++) {
        int jg  = wr * 32 + g;      // + mt*16
        int sd0 = wc * 8 + 2 * tq;
#pragma unroll
        for (int mt = 0; mt < 2; mt++) {
            int j = jg + mt * 16;
            sm[ sd0      * 132 + j]     = tf32f(acc[mt][nt][0]);
            sm[(sd0 + 1) * 132 + j]     = tf32f(acc[mt][nt][1]);
            sm[ sd0      * 132 + j + 8] = tf32f(acc[mt][nt][2]);
            sm[(sd0 + 1) * 132 + j + 8] = tf32f(acc[mt][nt][3]);
        }
        __syncthreads();
#pragma unroll
        for (int q = 0; q < 8; q++) {
            int idx = t + 256 * q;
            int r = idx >> 7, c = idx & 127;
            int dg = bn * 128 + (r >> 3) * 64 + nt * 8 + (r & 7);
            zt[(size_t)dg * N_ + jbase + c] = sm[r * 132 + c];
        }
        __syncthreads();
    }
}

// ---------------------------------------------------------------------------
// Kernel 2: combine s1/s2 partials
// ---------------------------------------------------------------------------
__global__ __launch_bounds__(256) void k_combine() {
    int id = blockIdx.x * 256 + threadIdx.x;
    g_s1[id] = g_s1p[0][id] + g_s1p[1][id] + g_s1p[2][id] + g_s1p[3][id];
    g_s2[id] = g_s2p[0][id] + g_s2p[1][id] + g_s2p[2][id] + g_s2p[3][id];
}

// ---------------------------------------------------------------------------
// Kernel 3: per-row mask stats (reg-slim: no ev[] array; l recomputed via shfl)
// ---------------------------------------------------------------------------
__global__ __launch_bounds__(256) void k_maskstat2(const int* __restrict__ adj) {
    __shared__ float s2s[N_];
    int row0 = blockIdx.x * 8;
    int b    = row0 >> 10;
    {
        const float4* s = (const float4*)(g_s2 + ((size_t)b << 10));
        ((float4*)s2s)[threadIdx.x] = s[threadIdx.x];
    }
    __syncthreads();
    int w = threadIdx.x >> 5, lane = threadIdx.x & 31;
    int row = row0 + w;
    float s1i = g_s1[row];
    const int* arow = adj + (size_t)row * N_;
    float m = -INFINITY;
    uint32_t word = 0;
#pragma unroll
    for (int k = 0; k < 32; k++) {
        int j = lane + 32 * k;
        bool conn = (arow[j] > 0);
        float x = s1i + s2s[j];
        x = (x >= 0.f) ? x : (ALPHA_ * x);
        uint32_t bal = __ballot_sync(0xffffffffu, conn);
        if (lane == k) word = bal;
        if (conn) m = fmaxf(m, x);
    }
#pragma unroll
    for (int o = 16; o > 0; o >>= 1) m = fmaxf(m, __shfl_xor_sync(0xffffffffu, m, o));
    float l = 0.f;
#pragma unroll
    for (int k = 0; k < 32; k++) {
        uint32_t wk = __shfl_sync(0xffffffffu, word, k);
        if ((wk >> lane) & 1u) {
            float x = s1i + s2s[lane + 32 * k];
            x = (x >= 0.f) ? x : (ALPHA_ * x);
            l += __expf(x - m);
        }
    }
#pragma unroll
    for (int o = 16; o > 0; o >>= 1) l += __shfl_xor_sync(0xffffffffu, l, o);
    g_bits[(size_t)row * 32 + lane] = word;
    if (lane == 0) { g_m[row] = m; g_linv[row] = 1.0f / l; }
}

// ---------------------------------------------------------------------------
// Kernel 4: out = ELU( P @ Z ) via mma.sync tf32 (unchanged from R4)
// ---------------------------------------------------------------------------
#define ZS0_  0
#define ZS1_  4608
#define PS_   9216
#define S2_   13824
#define SMF_  (13824 + 1024)

__global__ __launch_bounds__(256, 2) void k_attn3(const unsigned* __restrict__ bits,
                                                  float* __restrict__ out) {
    extern __shared__ __align__(16) float sm[];
    const uint32_t sb = smem_u32(sm);
    const uint32_t* smu = (const uint32_t*)sm;

    const int t    = threadIdx.x;
    const int lane = t & 31;
    const int wid  = t >> 5;
    const int wr   = wid & 3;
    const int wc   = wid >> 2;
    const int g    = lane >> 2;
    const int tq   = lane & 3;

    const int b  = blockIdx.z;
    const int i0 = blockIdx.x * 128;
    const int d0 = blockIdx.y * 128;

    ((float4*)(sm + S2_))[t] = ((const float4*)(g_s2 + ((size_t)b << 10)))[t];

    const int pi = t >> 1, jh = t & 1;
    const size_t grow = ((size_t)b << 10) + i0 + pi;
    const float s1i  = g_s1[grow];
    const float mi   = g_m[grow];
    const float linv = g_linv[grow];
    const unsigned* brow = bits + grow * 32;

    const char* ztb = (const char*)(g_zt + ((size_t)b << 18));

    float acc[2][8][4];
#pragma unroll
    for (int mt = 0; mt < 2; mt++)
#pragma unroll
        for (int nt = 0; nt < 8; nt++)
#pragma unroll
            for (int q = 0; q < 4; q++) acc[mt][nt][q] = 0.f;

    const int cdrow = t >> 3, cseg = t & 7;

#pragma unroll
    for (int q = 0; q < 4; q++) {
        int d = cdrow + 32 * q;
        CP_ASYNC16(sb + (ZS0_ + 0) * 4 + d * 144 + cseg * 16,
                   ztb + (size_t)(d0 + d) * 4096 + cseg * 16);
    }
    CP_COMMIT();
    __syncthreads();

    for (int c = 0; c < 32; c++) {
        {
            uint32_t word = __ldg(brow + c);
            float* prow = sm + PS_ + pi * 36 + jh * 16;
            const float* s2c = sm + S2_ + c * 32 + jh * 16;
#pragma unroll
            for (int jj = 0; jj < 16; jj += 2) {
                float x0 = s1i + s2c[jj];
                float x1 = s1i + s2c[jj + 1];
                x0 = (x0 >= 0.f) ? x0 : (ALPHA_ * x0);
                x1 = (x1 >= 0.f) ? x1 : (ALPHA_ * x1);
                int jl = jh * 16 + jj;
                float e0 = ((word >> jl) & 1u) ? x0 : NEGMASK;
                float e1 = ((word >> (jl + 1)) & 1u) ? x1 : NEGMASK;
                float2 p;
                p.x = __uint_as_float(tf32u(__expf(e0 - mi) * linv));
                p.y = __uint_as_float(tf32u(__expf(e1 - mi) * linv));
                *(float2*)(prow + jj) = p;
            }
        }
        if (c < 31) {
            uint32_t zoff = ((c + 1) & 1) ? ZS1_ : ZS0_;
#pragma unroll
            for (int q = 0; q < 4; q++) {
                int d = cdrow + 32 * q;
                CP_ASYNC16(sb + zoff * 4 + d * 144 + cseg * 16,
                           ztb + (size_t)(d0 + d) * 4096 + (size_t)(c + 1) * 128 + cseg * 16);
            }
            CP_COMMIT();
            CP_WAIT1();
        } else {
            CP_WAIT0();
        }
        __syncthreads();

        {
            const uint32_t zofs = ((c & 1) ? ZS1_ : ZS0_);
            const int nb = wc * 64 + g;
            const int rb = wr * 32 + g;
#pragma unroll
            for (int k0 = 0; k0 < 32; k0 += 8) {
                uint32_t bf[8][2];
#pragma unroll
                for (int nt = 0; nt < 8; nt++) {
                    int base = zofs + (nb + nt * 8) * 36 + k0 + tq;
                    bf[nt][0] = smu[base];
                    bf[nt][1] = smu[base + 4];
                }
#pragma unroll
                for (int mt = 0; mt < 2; mt++) {
                    int ab = PS_ + (rb + mt * 16) * 36 + k0 + tq;
                    uint32_t a0 = smu[ab];
                    uint32_t a1 = smu[ab + 8 * 36];
                    uint32_t a2 = smu[ab + 4];
                    uint32_t a3 = smu[ab + 8 * 36 + 4];
#pragma unroll
                    for (int nt = 0; nt < 8; nt++)
                        mma_tf32(acc[mt][nt], a0, a1, a2, a3, bf[nt][0], bf[nt][1]);
                }
            }
        }
        __syncthreads();
    }

#pragma unroll
    for (int mt = 0; mt < 2; mt++) {
        int row0 = i0 + wr * 32 + mt * 16 + g;
        float* o0 = out + (((size_t)b << 10) + row0) * D_ + d0 + wc * 64 + 2 * tq;
        float* o1 = o0 + 8 * D_;
#pragma unroll
        for (int nt = 0; nt < 8; nt++) {
            float v0 = acc[mt][nt][0], v1 = acc[mt][nt][1];
            float v2 = acc[mt][nt][2], v3 = acc[mt][nt][3];
            float2 r0, r1;
            r0.x = (v0 > 0.f) ? v0 : expm1f(v0);
            r0.y = (v1 > 0.f) ? v1 : expm1f(v1);
            r1.x = (v2 > 0.f) ? v2 : expm1f(v2);
            r1.y = (v3 > 0.f) ? v3 : expm1f(v3);
            *(float2*)(o0 + nt * 8) = r0;
            *(float2*)(o1 + nt * 8) = r1;
        }
    }
}

// ---------------------------------------------------------------------------
extern "C" void kernel_launch(void* const* d_in, const int* in_sizes, int n_in,
                              void* d_out, int out_size) {
    const float* h    = (const float*)d_in[0];
    const int*   adj  = (const int*)d_in[1];
    const float* W    = (const float*)d_in[2];
    const float* bias = (const float*)d_in[3];
    const float* a    = (const float*)d_in[4];
    float* out = (float*)d_out;
    (void)in_sizes; (void)n_in; (void)out_size;

    cudaFuncSetAttribute(k_zgemm_tc, cudaFuncAttributeMaxDynamicSharedMemorySize, ZG_SMEMB);
    cudaFuncSetAttribute(k_attn3, cudaFuncAttributeMaxDynamicSharedMemorySize,
                         SMF_ * sizeof(float));

    unsigned* bits_p;
    cudaGetSymbolAddress((void**)&bits_p, g_bits);

    k_zgemm_tc<<<dim3(2, 256), 256, ZG_SMEMB>>>(h, W, bias, a);
    k_combine<<<128, 256>>>();
    k_maskstat2<<<(B_ * N_) / 8, 256>>>(adj);
    k_attn3<<<dim3(8, 2, 32), 256, SMF_ * sizeof(float)>>>(bits_p, out);
}

// round 6
// speedup vs baseline: 1.0005x; 1.0005x over previous
#include <cuda_runtime.h>
#include <math.h>
#include <stdint.h>

#define B_  32
#define N_  1024
#define D_  256
#define NEGMASK (-9.0e15f)
#define ALPHA_  0.2f

// ---------------- device scratch ----------------
__device__ float g_zt[B_ * N_ * D_];     // zt [b][d][j]  (tf32-rounded)
__device__ float g_s1[B_ * N_];
__device__ float g_s2[B_ * N_];
__device__ float g_s1p[4][B_ * N_];      // partials (bn*2+wc)
__device__ float g_s2p[4][B_ * N_];
__device__ float g_m [B_ * N_];
__device__ float g_linv[B_ * N_];
__device__ unsigned g_bits[B_ * N_ * 32];  // adj bitmask

// ---------------- helpers ----------------
__device__ __forceinline__ uint32_t smem_u32(const void* p) {
    uint32_t a;
    asm("{ .reg .u64 t; cvta.to.shared.u64 t, %1; cvt.u32.u64 %0, t; }" : "=r"(a) : "l"(p));
    return a;
}
__device__ __forceinline__ uint32_t tf32u(float f) {
    uint32_t u; asm("cvt.rna.tf32.f32 %0, %1;" : "=r"(u) : "f"(f));
    return u;
}
__device__ __forceinline__ float tf32f(float f) { return __uint_as_float(tf32u(f)); }

#define CP_ASYNC16(sm, gp) \
    asm volatile("cp.async.cg.shared.global [%0], [%1], 16;" :: "r"(sm), "l"(gp) : "memory")
#define CP_COMMIT()  asm volatile("cp.async.commit_group;" ::: "memory")
#define CP_WAIT0()   asm volatile("cp.async.wait_group 0;" ::: "memory")
#define CP_WAIT1()   asm volatile("cp.async.wait_group 1;" ::: "memory")

__device__ __forceinline__ void mma_tf32(float* c, uint32_t a0, uint32_t a1,
                                         uint32_t a2, uint32_t a3,
                                         uint32_t b0, uint32_t b1) {
    asm volatile(
        "mma.sync.aligned.m16n8k8.row.col.f32.tf32.tf32.f32 "
        "{%0,%1,%2,%3}, {%4,%5,%6,%7}, {%8,%9}, {%0,%1,%2,%3};"
        : "+f"(c[0]), "+f"(c[1]), "+f"(c[2]), "+f"(c[3])
        : "r"(a0), "r"(a1), "r"(a2), "r"(a3), "r"(b0), "r"(b1));
}

// ---------------------------------------------------------------------------
// Kernel 1: fused z-GEMM (3xTF32, ~fp32 precision) + bias + s1/s2 partials
//           + transposed tf32 zt store.  CTA = 128 rows x 128 cols.
// grid (bn=2, bm=256), 256 threads, 8 warps of 32x64.
// smem: double-buffered A[128][36], B[128][36] fp32; stage tile reuses buf0.
// ---------------------------------------------------------------------------
#define ZG_BUF  9216                    // floats per buffer (A 4608 + B 4608)
#define ZG_SMEMB (2 * ZG_BUF * 4)       // 73728 bytes

__global__ __launch_bounds__(256) void k_zgemm_tc(const float* __restrict__ h,
                                                  const float* __restrict__ W,
                                                  const float* __restrict__ bias,
                                                  const float* __restrict__ av) {
    extern __shared__ __align__(16) float sm[];
    const int t    = threadIdx.x;
    const int lane = t & 31;
    const int wid  = t >> 5;
    const int wr   = wid & 3;
    const int wc   = wid >> 2;
    const int g    = lane >> 2;
    const int tq   = lane & 3;

    const int bn = blockIdx.x;          // d-half
    const int bm = blockIdx.y;          // row block
    const int R0 = bm * 128;            // global row (b*1024 + j)
    const uint32_t sb = smem_u32(sm);

    const float* hA = h + (size_t)R0 * D_;
    const float* wB = W + (size_t)(bn * 128) * D_;

    float acc[2][8][4];
#pragma unroll
    for (int mt = 0; mt < 2; mt++)
#pragma unroll
        for (int nt = 0; nt < 8; nt++)
#pragma unroll
            for (int q = 0; q < 4; q++) acc[mt][nt][q] = 0.f;

    // ---- prologue: chunk 0 -> buf 0
#pragma unroll
    for (int q = 0; q < 4; q++) {
        int idx = t + 256 * q, r = idx >> 3, s = idx & 7;
        CP_ASYNC16(sb + (0 + r * 36 + s * 4) * 4,    hA + (size_t)r * D_ + s * 4);
        CP_ASYNC16(sb + (4608 + r * 36 + s * 4) * 4, wB + (size_t)r * D_ + s * 4);
    }
    CP_COMMIT();

    for (int kc = 0; kc < 8; kc++) {
        if (kc < 7) {
            uint32_t bo = ((kc + 1) & 1) * ZG_BUF;
#pragma unroll
            for (int q = 0; q < 4; q++) {
                int idx = t + 256 * q, r = idx >> 3, s = idx & 7;
                CP_ASYNC16(sb + (bo + r * 36 + s * 4) * 4,
                           hA + (size_t)r * D_ + (kc + 1) * 32 + s * 4);
                CP_ASYNC16(sb + (bo + 4608 + r * 36 + s * 4) * 4,
                           wB + (size_t)r * D_ + (kc + 1) * 32 + s * 4);
            }
            CP_COMMIT();
            CP_WAIT1();
        } else {
            CP_WAIT0();
        }
        __syncthreads();

        const int aofs = (kc & 1) * ZG_BUF;
        const int bofs = aofs + 4608;
#pragma unroll
        for (int k0 = 0; k0 < 32; k0 += 8) {
            uint32_t bh[8][2], bl[8][2];
#pragma unroll
            for (int nt = 0; nt < 8; nt++) {
                int base = bofs + (wc * 64 + nt * 8 + g) * 36 + k0 + tq;
                float f0 = sm[base], f1 = sm[base + 4];
                bh[nt][0] = tf32u(f0);
                bl[nt][0] = tf32u(f0 - __uint_as_float(bh[nt][0]));
                bh[nt][1] = tf32u(f1);
                bl[nt][1] = tf32u(f1 - __uint_as_float(bh[nt][1]));
            }
#pragma unroll
            for (int mt = 0; mt < 2; mt++) {
                int ab = aofs + (wr * 32 + mt * 16 + g) * 36 + k0 + tq;
                float f0 = sm[ab],          f1 = sm[ab + 8 * 36];
                float f2 = sm[ab + 4],      f3 = sm[ab + 8 * 36 + 4];
                uint32_t ah0 = tf32u(f0), al0 = tf32u(f0 - __uint_as_float(ah0));
                uint32_t ah1 = tf32u(f1), al1 = tf32u(f1 - __uint_as_float(ah1));
                uint32_t ah2 = tf32u(f2), al2 = tf32u(f2 - __uint_as_float(ah2));
                uint32_t ah3 = tf32u(f3), al3 = tf32u(f3 - __uint_as_float(ah3));
#pragma unroll
                for (int nt = 0; nt < 8; nt++) {
                    mma_tf32(acc[mt][nt], ah0, ah1, ah2, ah3, bh[nt][0], bh[nt][1]);
                    mma_tf32(acc[mt][nt], ah0, ah1, ah2, ah3, bl[nt][0], bl[nt][1]);
                    mma_tf32(acc[mt][nt], al0, al1, al2, al3, bh[nt][0], bh[nt][1]);
                }
            }
        }
        __syncthreads();
    }

    // ---- epilogue: bias + s1/s2 partial dots
    float s1g[2] = {0.f, 0.f}, s1h[2] = {0.f, 0.f};
    float s2g[2] = {0.f, 0.f}, s2h[2] = {0.f, 0.f};
    const int colbase = bn * 128 + wc * 64;
#pragma unroll
    for (int nt = 0; nt < 8; nt++) {
        int c0 = colbase + nt * 8 + 2 * tq;
        float b0  = __ldg(bias + c0),        b1  = __ldg(bias + c0 + 1);
        float a10 = __ldg(av + c0),          a11 = __ldg(av + c0 + 1);
        float a20 = __ldg(av + D_ + c0),     a21 = __ldg(av + D_ + c0 + 1);
#pragma unroll
        for (int mt = 0; mt < 2; mt++) {
            acc[mt][nt][0] += b0; acc[mt][nt][1] += b1;
            acc[mt][nt][2] += b0; acc[mt][nt][3] += b1;
            s1g[mt] += acc[mt][nt][0] * a10 + acc[mt][nt][1] * a11;
            s1h[mt] += acc[mt][nt][2] * a10 + acc[mt][nt][3] * a11;
            s2g[mt] += acc[mt][nt][0] * a20 + acc[mt][nt][1] * a21;
            s2h[mt] += acc[mt][nt][2] * a20 + acc[mt][nt][3] * a21;
        }
    }
#pragma unroll
    for (int o = 1; o <= 2; o <<= 1) {
#pragma unroll
        for (int mt = 0; mt < 2; mt++) {
            s1g[mt] += __shfl_xor_sync(0xffffffffu, s1g[mt], o);
            s1h[mt] += __shfl_xor_sync(0xffffffffu, s1h[mt], o);
            s2g[mt] += __shfl_xor_sync(0xffffffffu, s2g[mt], o);
            s2h[mt] += __shfl_xor_sync(0xffffffffu, s2h[mt], o);
        }
    }
    if (tq == 0) {
        int part = bn * 2 + wc;
#pragma unroll
        for (int mt = 0; mt < 2; mt++) {
            int row = R0 + wr * 32 + mt * 16 + g;
            g_s1p[part][row]     = s1g[mt];
            g_s1p[part][row + 8] = s1h[mt];
            g_s2p[part][row]     = s2g[mt];
            g_s2p[part][row + 8] = s2h[mt];
        }
    }

    // ---- transposed tf32 zt store via smem staging (16 d x 128 j, reuse buf0)
    const int b_    = R0 >> 10;
    const int jbase = R0 & 1023;
    float* zt = g_zt + ((size_t)b_ << 18);
#pragma unroll 1
    for (int nt = 0; nt < 8; nt++) {
        int jg  = wr * 32 + g;      // + mt*16
        int sd0 = wc * 8 + 2 * tq;
#pragma unroll
        for (int mt = 0; mt < 2; mt++) {
            int j = jg + mt * 16;
            sm[ sd0      * 132 + j]     = tf32f(acc[mt][nt][0]);
            sm[(sd0 + 1) * 132 + j]     = tf32f(acc[mt][nt][1]);
            sm[ sd0      * 132 + j + 8] = tf32f(acc[mt][nt][2]);
            sm[(sd0 + 1) * 132 + j + 8] = tf32f(acc[mt][nt][3]);
        }
        __syncthreads();
#pragma unroll
        for (int q = 0; q < 8; q++) {
            int idx = t + 256 * q;
            int r = idx >> 7, c = idx & 127;
            int dg = bn * 128 + (r >> 3) * 64 + nt * 8 + (r & 7);
            zt[(size_t)dg * N_ + jbase + c] = sm[r * 132 + c];
        }
        __syncthreads();
    }
}

// ---------------------------------------------------------------------------
// Kernel 2: combine s1/s2 partials
// ---------------------------------------------------------------------------
__global__ __launch_bounds__(256) void k_combine() {
    int id = blockIdx.x * 256 + threadIdx.x;
    g_s1[id] = g_s1p[0][id] + g_s1p[1][id] + g_s1p[2][id] + g_s1p[3][id];
    g_s2[id] = g_s2p[0][id] + g_s2p[1][id] + g_s2p[2][id] + g_s2p[3][id];
}

// ---------------------------------------------------------------------------
// Kernel 3: per-row mask stats (reg-slim: no ev[] array; l recomputed via shfl)
// ---------------------------------------------------------------------------
__global__ __launch_bounds__(256) void k_maskstat2(const int* __restrict__ adj) {
    __shared__ float s2s[N_];
    int row0 = blockIdx.x * 8;
    int b    = row0 >> 10;
    {
        const float4* s = (const float4*)(g_s2 + ((size_t)b << 10));
        ((float4*)s2s)[threadIdx.x] = s[threadIdx.x];
    }
    __syncthreads();
    int w = threadIdx.x >> 5, lane = threadIdx.x & 31;
    int row = row0 + w;
    float s1i = g_s1[row];
    const int* arow = adj + (size_t)row * N_;
    float m = -INFINITY;
    uint32_t word = 0;
#pragma unroll
    for (int k = 0; k < 32; k++) {
        int j = lane + 32 * k;
        bool conn = (arow[j] > 0);
        float x = s1i + s2s[j];
        x = (x >= 0.f) ? x : (ALPHA_ * x);
        uint32_t bal = __ballot_sync(0xffffffffu, conn);
        if (lane == k) word = bal;
        if (conn) m = fmaxf(m, x);
    }
#pragma unroll
    for (int o = 16; o > 0; o >>= 1) m = fmaxf(m, __shfl_xor_sync(0xffffffffu, m, o));
    float l = 0.f;
#pragma unroll
    for (int k = 0; k < 32; k++) {
        uint32_t wk = __shfl_sync(0xffffffffu, word, k);
        if ((wk >> lane) & 1u) {
            float x = s1i + s2s[lane + 32 * k];
            x = (x >= 0.f) ? x : (ALPHA_ * x);
            l += __expf(x - m);
        }
    }
#pragma unroll
    for (int o = 16; o > 0; o >>= 1) l += __shfl_xor_sync(0xffffffffu, l, o);
    g_bits[(size_t)row * 32 + lane] = word;
    if (lane == 0) { g_m[row] = m; g_linv[row] = 1.0f / l; }
}

// ---------------------------------------------------------------------------
// Kernel 4: out = ELU( P @ Z ) via mma.sync tf32 (unchanged from R4)
// ---------------------------------------------------------------------------
#define ZS0_  0
#define ZS1_  4608
#define PS_   9216
#define S2_   13824
#define SMF_  (13824 + 1024)

__global__ __launch_bounds__(256, 2) void k_attn3(const unsigned* __restrict__ bits,
                                                  float* __restrict__ out) {
    extern __shared__ __align__(16) float sm[];
    const uint32_t sb = smem_u32(sm);
    const uint32_t* smu = (const uint32_t*)sm;

    const int t    = threadIdx.x;
    const int lane = t & 31;
    const int wid  = t >> 5;
    const int wr   = wid & 3;
    const int wc   = wid >> 2;
    const int g    = lane >> 2;
    const int tq   = lane & 3;

    const int b  = blockIdx.z;
    const int i0 = blockIdx.x * 128;
    const int d0 = blockIdx.y * 128;

    ((float4*)(sm + S2_))[t] = ((const float4*)(g_s2 + ((size_t)b << 10)))[t];

    const int pi = t >> 1, jh = t & 1;
    const size_t grow = ((size_t)b << 10) + i0 + pi;
    const float s1i  = g_s1[grow];
    const float mi   = g_m[grow];
    const float linv = g_linv[grow];
    const unsigned* brow = bits + grow * 32;

    const char* ztb = (const char*)(g_zt + ((size_t)b << 18));

    float acc[2][8][4];
#pragma unroll
    for (int mt = 0; mt < 2; mt++)
#pragma unroll
        for (int nt = 0; nt < 8; nt++)
#pragma unroll
            for (int q = 0; q < 4; q++) acc[mt][nt][q] = 0.f;

    const int cdrow = t >> 3, cseg = t & 7;

#pragma unroll
    for (int q = 0; q < 4; q++) {
        int d = cdrow + 32 * q;
        CP_ASYNC16(sb + (ZS0_ + 0) * 4 + d * 144 + cseg * 16,
                   ztb + (size_t)(d0 + d) * 4096 + cseg * 16);
    }
    CP_COMMIT();
    __syncthreads();

    for (int c = 0; c < 32; c++) {
        {
            uint32_t word = __ldg(brow + c);
            float* prow = sm + PS_ + pi * 36 + jh * 16;
            const float* s2c = sm + S2_ + c * 32 + jh * 16;
#pragma unroll
            for (int jj = 0; jj < 16; jj += 2) {
                float x0 = s1i + s2c[jj];
                float x1 = s1i + s2c[jj + 1];
                x0 = (x0 >= 0.f) ? x0 : (ALPHA_ * x0);
                x1 = (x1 >= 0.f) ? x1 : (ALPHA_ * x1);
                int jl = jh * 16 + jj;
                float e0 = ((word >> jl) & 1u) ? x0 : NEGMASK;
                float e1 = ((word >> (jl + 1)) & 1u) ? x1 : NEGMASK;
                float2 p;
                p.x = __uint_as_float(tf32u(__expf(e0 - mi) * linv));
                p.y = __uint_as_float(tf32u(__expf(e1 - mi) * linv));
                *(float2*)(prow + jj) = p;
            }
        }
        if (c < 31) {
            uint32_t zoff = ((c + 1) & 1) ? ZS1_ : ZS0_;
#pragma unroll
            for (int q = 0; q < 4; q++) {
                int d = cdrow + 32 * q;
                CP_ASYNC16(sb + zoff * 4 + d * 144 + cseg * 16,
                           ztb + (size_t)(d0 + d) * 4096 + (size_t)(c + 1) * 128 + cseg * 16);
            }
            CP_COMMIT();
            CP_WAIT1();
        } else {
            CP_WAIT0();
        }
        __syncthreads();

        {
            const uint32_t zofs = ((c & 1) ? ZS1_ : ZS0_);
            const int nb = wc * 64 + g;
            const int rb = wr * 32 + g;
#pragma unroll
            for (int k0 = 0; k0 < 32; k0 += 8) {
                uint32_t bf[8][2];
#pragma unroll
                for (int nt = 0; nt < 8; nt++) {
                    int base = zofs + (nb + nt * 8) * 36 + k0 + tq;
                    bf[nt][0] = smu[base];
                    bf[nt][1] = smu[base + 4];
                }
#pragma unroll
                for (int mt = 0; mt < 2; mt++) {
                    int ab = PS_ + (rb + mt * 16) * 36 + k0 + tq;
                    uint32_t a0 = smu[ab];
                    uint32_t a1 = smu[ab + 8 * 36];
                    uint32_t a2 = smu[ab + 4];
                    uint32_t a3 = smu[ab + 8 * 36 + 4];
#pragma unroll
                    for (int nt = 0; nt < 8; nt++)
                        mma_tf32(acc[mt][nt], a0, a1, a2, a3, bf[nt][0], bf[nt][1]);
                }
            }
        }
        __syncthreads();
    }

#pragma unroll
    for (int mt = 0; mt < 2; mt++) {
        int row0 = i0 + wr * 32 + mt * 16 + g;
        float* o0 = out + (((size_t)b << 10) + row0) * D_ + d0 + wc * 64 + 2 * tq;
        float* o1 = o0 + 8 * D_;
#pragma unroll
        for (int nt = 0; nt < 8; nt++) {
            float v0 = acc[mt][nt][0], v1 = acc[mt][nt][1];
            float v2 = acc[mt][nt][2], v3 = acc[mt][nt][3];
            float2 r0, r1;
            r0.x = (v0 > 0.f) ? v0 : expm1f(v0);
            r0.y = (v1 > 0.f) ? v1 : expm1f(v1);
            r1.x = (v2 > 0.f) ? v2 : expm1f(v2);
            r1.y = (v3 > 0.f) ? v3 : expm1f(v3);
            *(float2*)(o0 + nt * 8) = r0;
            *(float2*)(o1 + nt * 8) = r1;
        }
    }
}

// ---------------------------------------------------------------------------
extern "C" void kernel_launch(void* const* d_in, const int* in_sizes, int n_in,
                              void* d_out, int out_size) {
    const float* h    = (const float*)d_in[0];
    const int*   adj  = (const int*)d_in[1];
    const float* W    = (const float*)d_in[2];
    const float* bias = (const float*)d_in[3];
    const float* a    = (const float*)d_in[4];
    float* out = (float*)d_out;
    (void)in_sizes; (void)n_in; (void)out_size;

    cudaFuncSetAttribute(k_zgemm_tc, cudaFuncAttributeMaxDynamicSharedMemorySize, ZG_SMEMB);
    cudaFuncSetAttribute(k_attn3, cudaFuncAttributeMaxDynamicSharedMemorySize,
                         SMF_ * sizeof(float));

    unsigned* bits_p;
    cudaGetSymbolAddress((void**)&bits_p, g_bits);

    k_zgemm_tc<<<dim3(2, 256), 256, ZG_SMEMB>>>(h, W, bias, a);
    k_combine<<<128, 256>>>();
    k_maskstat2<<<(B_ * N_) / 8, 256>>>(adj);
    k_attn3<<<dim3(8, 2, 32), 256, SMF_ * sizeof(float)>>>(bits_p, out);
}